// round 1
// baseline (speedup 1.0000x reference)
#include <cuda_runtime.h>
#include <cstdint>

#define NNA 40000
#define NNB 40000
#define EE  400000
#define HH  8
#define DD  256   // H*C
#define CCH 32

// ---------------- scratch (device globals; no allocations allowed) ----------
__device__ __align__(16) float g_hA[NNA * DD];
__device__ __align__(16) float g_hB[NNB * DD];
__device__ __align__(16) float g_relAB[NNB * DD];   // rel 0: A->B, dst in B
__device__ __align__(16) float g_relBA[NNA * DD];   // rel 1: B->A, dst in A
__device__ __align__(16) float g_relAA[NNA * DD];   // rel 2: A->A, dst in A
__device__ __align__(16) float g_al0[NNA * HH];
__device__ __align__(16) float g_ar0[NNB * HH];
__device__ __align__(16) float g_al1[NNB * HH];
__device__ __align__(16) float g_ar1[NNA * HH];
__device__ __align__(16) float g_al2[NNA * HH];
__device__ __align__(16) float g_ar2[NNA * HH];
__device__ __align__(16) unsigned g_menc[3][NNA * HH];
__device__ __align__(16) float    g_den [3][NNA * HH];
__device__ __align__(16) float g_ebuf[EE * HH];     // reused across relations (stream-ordered)

// ---------------- helpers ---------------------------------------------------
__device__ __forceinline__ unsigned fenc(float f) {
    unsigned u = __float_as_uint(f);
    return (u & 0x80000000u) ? ~u : (u | 0x80000000u);
}
__device__ __forceinline__ float fdec(unsigned u) {
    unsigned v = (u & 0x80000000u) ? (u & 0x7FFFFFFFu) : ~u;
    return __uint_as_float(v);
}
__device__ __forceinline__ float leaky(float x) { return x > 0.f ? x : 0.2f * x; }
__device__ __forceinline__ float warpsum(float v) {
#pragma unroll
    for (int o = 16; o > 0; o >>= 1) v += __shfl_xor_sync(0xffffffffu, v, o);
    return v;
}

// ---------------- zero init -------------------------------------------------
__global__ void zero_all() {
    int i = blockIdx.x * blockDim.x + threadIdx.x;   // grid = 2,560,000 threads
    float4 z = make_float4(0.f, 0.f, 0.f, 0.f);
    ((float4*)g_relAB)[i] = z;
    ((float4*)g_relBA)[i] = z;
    ((float4*)g_relAA)[i] = z;
    if (i < 240000) {                                 // 3*320000 u32 = 240000 uint4
        ((uint4*)g_menc)[i] = make_uint4(0u, 0u, 0u, 0u);
        ((float4*)g_den)[i] = z;
    }
}

// ---------------- GEMM: h = X @ W + b  (M=40000, N=K=256) -------------------
#define BM 64
#define BN 64
#define BK 16
template <int WHICH>
__global__ __launch_bounds__(256) void gemm_bias(const float* __restrict__ X,
                                                 const float* __restrict__ W,
                                                 const float* __restrict__ bias) {
    float* out = WHICH ? g_hB : g_hA;
    __shared__ float As[BK][BM];
    __shared__ float Bs[BK][BN];
    int tid = threadIdx.x;
    int bm = blockIdx.x * BM;
    int bn = blockIdx.y * BN;
    int ty = tid >> 4, tx = tid & 15;

    int arow = tid >> 2;
    int akv  = (tid & 3) * 4;
    int brow = tid >> 4;
    int bcol = (tid & 15) * 4;

    float acc[4][4] = {};
    for (int k0 = 0; k0 < 256; k0 += BK) {
        float4 av = *(const float4*)(X + (size_t)(bm + arow) * 256 + k0 + akv);
        float4 bv = *(const float4*)(W + (size_t)(k0 + brow) * 256 + bn + bcol);
        As[akv + 0][arow] = av.x;
        As[akv + 1][arow] = av.y;
        As[akv + 2][arow] = av.z;
        As[akv + 3][arow] = av.w;
        *(float4*)(&Bs[brow][bcol]) = bv;
        __syncthreads();
#pragma unroll
        for (int kk = 0; kk < BK; kk++) {
            float4 ra = *(const float4*)(&As[kk][ty * 4]);
            float4 rb = *(const float4*)(&Bs[kk][tx * 4]);
            float ar_[4] = {ra.x, ra.y, ra.z, ra.w};
            float br_[4] = {rb.x, rb.y, rb.z, rb.w};
#pragma unroll
            for (int i = 0; i < 4; i++)
#pragma unroll
                for (int j = 0; j < 4; j++) acc[i][j] += ar_[i] * br_[j];
        }
        __syncthreads();
    }
    float4 bb = *(const float4*)(bias + bn + tx * 4);
#pragma unroll
    for (int i = 0; i < 4; i++) {
        int row = bm + ty * 4 + i;
        float4 o;
        o.x = acc[i][0] + bb.x;
        o.y = acc[i][1] + bb.y;
        o.z = acc[i][2] + bb.z;
        o.w = acc[i][3] + bb.w;
        *(float4*)(out + (size_t)row * 256 + bn + tx * 4) = o;
    }
}

// ---------------- per-node attention scalars --------------------------------
__global__ void alphas_kernel(const float* __restrict__ attn_l,
                              const float* __restrict__ attn_r) {
    int tid = blockIdx.x * blockDim.x + threadIdx.x;   // (NA+NB)*H threads
    if (tid < NNA * HH) {
        int n = tid >> 3, h = tid & 7;
        const float4* hp = (const float4*)(g_hA + (size_t)n * DD + h * 32);
        const float4* l0 = (const float4*)(attn_l + 0 * DD + h * 32);
        const float4* r1 = (const float4*)(attn_r + 1 * DD + h * 32);
        const float4* l2 = (const float4*)(attn_l + 2 * DD + h * 32);
        const float4* r2 = (const float4*)(attn_r + 2 * DD + h * 32);
        float s0 = 0, s1 = 0, s2 = 0, s3 = 0;
#pragma unroll
        for (int c = 0; c < 8; c++) {
            float4 v = hp[c];
            float4 a;
            a = l0[c]; s0 += v.x * a.x + v.y * a.y + v.z * a.z + v.w * a.w;
            a = r1[c]; s1 += v.x * a.x + v.y * a.y + v.z * a.z + v.w * a.w;
            a = l2[c]; s2 += v.x * a.x + v.y * a.y + v.z * a.z + v.w * a.w;
            a = r2[c]; s3 += v.x * a.x + v.y * a.y + v.z * a.z + v.w * a.w;
        }
        g_al0[tid] = s0;
        g_ar1[tid] = s1;
        g_al2[tid] = s2;
        g_ar2[tid] = s3;
    } else {
        int t = tid - NNA * HH;
        if (t >= NNB * HH) return;
        int n = t >> 3, h = t & 7;
        const float4* hp = (const float4*)(g_hB + (size_t)n * DD + h * 32);
        const float4* l1 = (const float4*)(attn_l + 1 * DD + h * 32);
        const float4* r0 = (const float4*)(attn_r + 0 * DD + h * 32);
        float s0 = 0, s1 = 0;
#pragma unroll
        for (int c = 0; c < 8; c++) {
            float4 v = hp[c];
            float4 a;
            a = l1[c]; s0 += v.x * a.x + v.y * a.y + v.z * a.z + v.w * a.w;
            a = r0[c]; s1 += v.x * a.x + v.y * a.y + v.z * a.z + v.w * a.w;
        }
        g_al1[t] = s0;
        g_ar0[t] = s1;
    }
}

// ---------------- edge pass 1: logits + segment max -------------------------
template <int REL>
__global__ void edge_attn_max(const int* __restrict__ edge) {
    int tid = blockIdx.x * blockDim.x + threadIdx.x;   // E*H threads
    if (tid >= EE * HH) return;
    int e = tid >> 3, h = tid & 7;
    int src = edge[e];
    int dst = edge[EE + e];
    const float* al = (REL == 0) ? g_al0 : (REL == 1) ? g_al1 : g_al2;
    const float* ar = (REL == 0) ? g_ar0 : (REL == 1) ? g_ar1 : g_ar2;
    float v = leaky(al[src * HH + h] + ar[dst * HH + h]);
    g_ebuf[tid] = v;
    atomicMax(&g_menc[REL][dst * HH + h], fenc(v));
}

// ---------------- edge pass 2: exp + segment sum ----------------------------
template <int REL>
__global__ void edge_exp_sum(const int* __restrict__ edge) {
    int tid = blockIdx.x * blockDim.x + threadIdx.x;
    if (tid >= EE * HH) return;
    int e = tid >> 3, h = tid & 7;
    int dst = edge[EE + e];
    float m = fdec(g_menc[REL][dst * HH + h]);
    float ex = __expf(g_ebuf[tid] - m);
    g_ebuf[tid] = ex;
    atomicAdd(&g_den[REL][dst * HH + h], ex);
}

// ---------------- edge pass 3: weighted message scatter ---------------------
template <int REL>
__global__ void edge_message(const int* __restrict__ edge) {
    int gw   = (blockIdx.x * blockDim.x + threadIdx.x) >> 5;   // one warp per edge
    int lane = threadIdx.x & 31;
    if (gw >= EE) return;
    int src = edge[gw];
    int dst = edge[EE + gw];
    const float* hsrc = (REL == 1) ? g_hB : g_hA;
    float* rel = (REL == 0) ? g_relAB : (REL == 1) ? g_relBA : g_relAA;
    const float4* hp = (const float4*)(hsrc + (size_t)src * DD);
    float4* rp = (float4*)(rel + (size_t)dst * DD);
#pragma unroll
    for (int rep = 0; rep < 2; rep++) {
        int q = lane + rep * 32;          // 64 float4 per edge row
        int h = q >> 3;
        float alpha = g_ebuf[gw * 8 + h] / g_den[REL][dst * 8 + h];
        float4 v = hp[q];
        v.x *= alpha; v.y *= alpha; v.z *= alpha; v.w *= alpha;
        atomicAdd(rp + q, v);             // sm_90+ vector float4 atomic add
    }
}

// ---------------- beta combine (relation softmax) ---------------------------
__global__ void beta_combine_A(const float* __restrict__ rl,
                               const float* __restrict__ rr,
                               float* __restrict__ out) {
    int w    = (blockIdx.x * blockDim.x + threadIdx.x) >> 5;   // warp per node
    int lane = threadIdx.x & 31;
    if (w >= NNA) return;
    const float* hp = g_hA + (size_t)w * DD;
    const float* p0 = g_relBA + (size_t)w * DD;
    const float* p1 = g_relAA + (size_t)w * DD;
    float* op = out + (size_t)w * DD;
#pragma unroll
    for (int h = 0; h < HH; h++) {
        int o = h * 32 + lane;
        float a  = hp[o];
        float e0 = p0[o];
        float e1 = p1[o];
        float wl = rl[o];
        float wr = rr[o];
        float bl = warpsum(a * wl);
        float b0 = warpsum(e0 * wr);
        float b1 = warpsum(e1 * wr);
        float b2 = warpsum(a * wr);
        float s0 = leaky(bl + b0);
        float s1 = leaky(bl + b1);
        float s2 = leaky(bl + b2);
        float mx = fmaxf(s0, fmaxf(s1, s2));
        float x0 = __expf(s0 - mx), x1 = __expf(s1 - mx), x2 = __expf(s2 - mx);
        float inv = 1.f / (x0 + x1 + x2);
        float v = (e0 * x0 + e1 * x1 + a * x2) * inv;
        op[o] = v > 0.f ? v : 0.f;
    }
}

__global__ void beta_combine_B(const float* __restrict__ rl,
                               const float* __restrict__ rr,
                               float* __restrict__ out) {
    int w    = (blockIdx.x * blockDim.x + threadIdx.x) >> 5;
    int lane = threadIdx.x & 31;
    if (w >= NNB) return;
    const float* hp = g_hB + (size_t)w * DD;
    const float* p0 = g_relAB + (size_t)w * DD;
    float* op = out + (size_t)w * DD;
#pragma unroll
    for (int h = 0; h < HH; h++) {
        int o = h * 32 + lane;
        float a  = hp[o];
        float e0 = p0[o];
        float wl = rl[o];
        float wr = rr[o];
        float bl = warpsum(a * wl);
        float b0 = warpsum(e0 * wr);
        float b1 = warpsum(a * wr);
        float s0 = leaky(bl + b0);
        float s1 = leaky(bl + b1);
        float mx = fmaxf(s0, s1);
        float x0 = __expf(s0 - mx), x1 = __expf(s1 - mx);
        float inv = 1.f / (x0 + x1);
        float v = (e0 * x0 + a * x1) * inv;
        op[o] = v > 0.f ? v : 0.f;
    }
}

// ---------------- launch -----------------------------------------------------
extern "C" void kernel_launch(void* const* d_in, const int* in_sizes, int n_in,
                              void* d_out, int out_size) {
    const float* x_A    = (const float*)d_in[0];
    const float* x_B    = (const float*)d_in[1];
    const int*   e_ab   = (const int*)d_in[2];
    const int*   e_ba   = (const int*)d_in[3];
    const int*   e_aa   = (const int*)d_in[4];
    const float* W_A    = (const float*)d_in[5];
    const float* b_A    = (const float*)d_in[6];
    const float* W_B    = (const float*)d_in[7];
    const float* b_B    = (const float*)d_in[8];
    const float* attn_l = (const float*)d_in[9];
    const float* attn_r = (const float*)d_in[10];
    const float* rel_l_A = (const float*)d_in[11];
    const float* rel_r_A = (const float*)d_in[12];
    const float* rel_l_B = (const float*)d_in[13];
    const float* rel_r_B = (const float*)d_in[14];
    float* out = (float*)d_out;

    zero_all<<<10000, 256>>>();

    dim3 gg(625, 4);
    gemm_bias<0><<<gg, 256>>>(x_A, W_A, b_A);
    gemm_bias<1><<<gg, 256>>>(x_B, W_B, b_B);

    alphas_kernel<<<2500, 256>>>(attn_l, attn_r);

    // relation 0: A -> B
    edge_attn_max<0><<<12500, 256>>>(e_ab);
    edge_exp_sum<0><<<12500, 256>>>(e_ab);
    edge_message<0><<<50000, 256>>>(e_ab);
    // relation 1: B -> A
    edge_attn_max<1><<<12500, 256>>>(e_ba);
    edge_exp_sum<1><<<12500, 256>>>(e_ba);
    edge_message<1><<<50000, 256>>>(e_ba);
    // relation 2: A -> A
    edge_attn_max<2><<<12500, 256>>>(e_aa);
    edge_exp_sum<2><<<12500, 256>>>(e_aa);
    edge_message<2><<<50000, 256>>>(e_aa);

    beta_combine_A<<<5000, 256>>>(rel_l_A, rel_r_A, out);
    beta_combine_B<<<5000, 256>>>(rel_l_B, rel_r_B, out + (size_t)NNA * DD);
}

// round 4
// speedup vs baseline: 2.1603x; 2.1603x over previous
#include <cuda_runtime.h>
#include <cstdint>

#define NNA 40000
#define NNB 40000
#define EE  400000
#define HH  8
#define DD  256   // H*C
#define CCH 32

// ---------------- scratch (device globals; no allocations allowed) ----------
__device__ __align__(16) float g_hA[NNA * DD];
__device__ __align__(16) float g_hB[NNB * DD];
__device__ __align__(16) float g_relAB[NNB * DD];   // rel 0: A->B, dst in B
__device__ __align__(16) float g_relBA[NNA * DD];   // rel 1: B->A, dst in A
__device__ __align__(16) float g_relAA[NNA * DD];   // rel 2: A->A, dst in A
__device__ __align__(16) float g_al0[NNA * HH];
__device__ __align__(16) float g_ar0[NNB * HH];
__device__ __align__(16) float g_al1[NNB * HH];
__device__ __align__(16) float g_ar1[NNA * HH];
__device__ __align__(16) float g_al2[NNA * HH];
__device__ __align__(16) float g_ar2[NNA * HH];
__device__ __align__(16) unsigned g_menc[3][NNA * HH];
__device__ __align__(16) float    g_den [3][NNA * HH];
__device__ __align__(16) float g_ebuf[EE * HH];     // reused across relations (stream-ordered)

// ---------------- helpers ---------------------------------------------------
__device__ __forceinline__ unsigned fenc(float f) {
    unsigned u = __float_as_uint(f);
    return (u & 0x80000000u) ? ~u : (u | 0x80000000u);
}
__device__ __forceinline__ float fdec(unsigned u) {
    unsigned v = (u & 0x80000000u) ? (u & 0x7FFFFFFFu) : ~u;
    return __uint_as_float(v);
}
__device__ __forceinline__ float leaky(float x) { return x > 0.f ? x : 0.2f * x; }
__device__ __forceinline__ float warpsum(float v) {
#pragma unroll
    for (int o = 16; o > 0; o >>= 1) v += __shfl_xor_sync(0xffffffffu, v, o);
    return v;
}
__device__ __forceinline__ float sub8sum(float v) {
#pragma unroll
    for (int o = 1; o < 8; o <<= 1) v += __shfl_xor_sync(0xffffffffu, v, o);
    return v;
}
__device__ __forceinline__ float to_tf32(float x) {
    float r;
    asm("cvt.rna.tf32.f32 %0, %1;" : "=f"(r) : "f"(x));
    return r;
}
__device__ __forceinline__ void mma_tf32(float* d, const unsigned* a, const unsigned* b) {
    asm volatile(
        "mma.sync.aligned.m16n8k8.row.col.f32.tf32.tf32.f32 "
        "{%0,%1,%2,%3}, {%4,%5,%6,%7}, {%8,%9}, {%0,%1,%2,%3};"
        : "+f"(d[0]), "+f"(d[1]), "+f"(d[2]), "+f"(d[3])
        : "r"(a[0]), "r"(a[1]), "r"(a[2]), "r"(a[3]), "r"(b[0]), "r"(b[1]));
}

// ---------------- zero init -------------------------------------------------
__global__ void zero_all() {
    int i = blockIdx.x * blockDim.x + threadIdx.x;   // grid = 2,560,000 threads
    float4 z = make_float4(0.f, 0.f, 0.f, 0.f);
    ((float4*)g_relAB)[i] = z;
    ((float4*)g_relBA)[i] = z;
    ((float4*)g_relAA)[i] = z;
    if (i < 240000) {                                 // 3*320000 u32 = 240000 uint4
        ((uint4*)g_menc)[i] = make_uint4(0u, 0u, 0u, 0u);
        ((float4*)g_den)[i] = z;
    }
}

// ---------------- tf32 tensor-core GEMM: h = X @ W + b ----------------------
// M=40000, N=256, K=256. BM=128, BN=64, BK=32, 256 threads (8 warps 4x2),
// warp tile 32x32 = 2(m16) x 4(n8) mma tiles, k-steps of 8.
#define GBM 128
#define GBN 64
#define GBK 32
#define APAD 36
#define BPAD 72
template <int WHICH>
__global__ __launch_bounds__(256) void gemm_tf32(const float* __restrict__ X,
                                                 const float* __restrict__ W,
                                                 const float* __restrict__ bias) {
    float* out = WHICH ? g_hB : g_hA;
    __shared__ float As[GBM][APAD];   // [m][k]
    __shared__ float Bs[GBK][BPAD];   // [k][n]

    int tid  = threadIdx.x;
    int lane = tid & 31;
    int w    = tid >> 5;
    int wm   = w >> 1;                 // 0..3
    int wn   = w & 1;                  // 0..1
    int g    = lane >> 2;              // 0..7
    int tig  = lane & 3;               // 0..3
    int bm   = blockIdx.x * GBM;
    int bn   = blockIdx.y * GBN;

    // A-load mapping: 4 float4/thread
    int ar = tid >> 3;                 // 0..31
    int ac = (tid & 7) * 4;            // 0..28
    // B-load mapping: 2 float4/thread
    int br = tid >> 4;                 // 0..15
    int bc = (tid & 15) * 4;           // 0..60

    int arow[4];
#pragma unroll
    for (int i = 0; i < 4; i++) {
        int r = bm + ar + i * 32;
        arow[i] = r < NNA ? r : NNA - 1;
    }

    float acc[2][4][4] = {};
    float4 aReg[4], bReg[2];

    // prefetch k0 = 0
#pragma unroll
    for (int i = 0; i < 4; i++)
        aReg[i] = *(const float4*)(X + (size_t)arow[i] * 256 + ac);
#pragma unroll
    for (int i = 0; i < 2; i++)
        bReg[i] = *(const float4*)(W + (size_t)(br + i * 16) * 256 + bn + bc);

    for (int k0 = 0; k0 < 256; k0 += GBK) {
        // store (tf32-rounded) to smem
#pragma unroll
        for (int i = 0; i < 4; i++) {
            As[ar + i * 32][ac + 0] = to_tf32(aReg[i].x);
            As[ar + i * 32][ac + 1] = to_tf32(aReg[i].y);
            As[ar + i * 32][ac + 2] = to_tf32(aReg[i].z);
            As[ar + i * 32][ac + 3] = to_tf32(aReg[i].w);
        }
#pragma unroll
        for (int i = 0; i < 2; i++) {
            Bs[br + i * 16][bc + 0] = to_tf32(bReg[i].x);
            Bs[br + i * 16][bc + 1] = to_tf32(bReg[i].y);
            Bs[br + i * 16][bc + 2] = to_tf32(bReg[i].z);
            Bs[br + i * 16][bc + 3] = to_tf32(bReg[i].w);
        }
        __syncthreads();

        if (k0 + GBK < 256) {
            int kn = k0 + GBK;
#pragma unroll
            for (int i = 0; i < 4; i++)
                aReg[i] = *(const float4*)(X + (size_t)arow[i] * 256 + kn + ac);
#pragma unroll
            for (int i = 0; i < 2; i++)
                bReg[i] = *(const float4*)(W + (size_t)(kn + br + i * 16) * 256 + bn + bc);
        }

#pragma unroll
        for (int ks = 0; ks < 4; ks++) {
            int kk = ks * 8;
            unsigned af[2][4], bf[4][2];
#pragma unroll
            for (int mt = 0; mt < 2; mt++) {
                int mrow = wm * 32 + mt * 16 + g;
                af[mt][0] = __float_as_uint(As[mrow][kk + tig]);
                af[mt][1] = __float_as_uint(As[mrow + 8][kk + tig]);
                af[mt][2] = __float_as_uint(As[mrow][kk + tig + 4]);
                af[mt][3] = __float_as_uint(As[mrow + 8][kk + tig + 4]);
            }
#pragma unroll
            for (int nt = 0; nt < 4; nt++) {
                int ncol = wn * 32 + nt * 8 + g;
                bf[nt][0] = __float_as_uint(Bs[kk + tig][ncol]);
                bf[nt][1] = __float_as_uint(Bs[kk + tig + 4][ncol]);
            }
#pragma unroll
            for (int mt = 0; mt < 2; mt++)
#pragma unroll
                for (int nt = 0; nt < 4; nt++)
                    mma_tf32(acc[mt][nt], af[mt], bf[nt]);
        }
        __syncthreads();
    }

    // epilogue: bias + store
#pragma unroll
    for (int nt = 0; nt < 4; nt++) {
        int col = bn + wn * 32 + nt * 8 + tig * 2;
        float2 bb = *(const float2*)(bias + col);
#pragma unroll
        for (int mt = 0; mt < 2; mt++) {
            int r0 = bm + wm * 32 + mt * 16 + g;
            if (r0 < NNA) {
                float2 o = make_float2(acc[mt][nt][0] + bb.x, acc[mt][nt][1] + bb.y);
                *(float2*)(out + (size_t)r0 * 256 + col) = o;
            }
            int r1 = r0 + 8;
            if (r1 < NNA) {
                float2 o = make_float2(acc[mt][nt][2] + bb.x, acc[mt][nt][3] + bb.y);
                *(float2*)(out + (size_t)r1 * 256 + col) = o;
            }
        }
    }
}

// ---------------- per-node attention scalars (warp per node, coalesced) -----
__global__ void alphas_kernel(const float* __restrict__ attn_l,
                              const float* __restrict__ attn_r) {
    int w    = (blockIdx.x * blockDim.x + threadIdx.x) >> 5;  // warp = node
    int lane = threadIdx.x & 31;
    if (w >= NNA + NNB) return;
    int h0 = lane >> 3;        // chunk q=lane    -> head h0 (0..3)
    bool wr = (lane & 7) == 0;

    if (w < NNA) {
        const float4* hp = (const float4*)(g_hA + (size_t)w * DD);
        float4 v0 = hp[lane], v1 = hp[lane + 32];
        const float4* l0 = (const float4*)(attn_l);
        const float4* r1 = (const float4*)(attn_r + DD);
        const float4* l2 = (const float4*)(attn_l + 2 * DD);
        const float4* r2 = (const float4*)(attn_r + 2 * DD);
#pragma unroll
        for (int a = 0; a < 4; a++) {
            const float4* P = (a == 0) ? l0 : (a == 1) ? r1 : (a == 2) ? l2 : r2;
            float4 p0 = P[lane], p1 = P[lane + 32];
            float s0 = v0.x * p0.x + v0.y * p0.y + v0.z * p0.z + v0.w * p0.w;
            float s1 = v1.x * p1.x + v1.y * p1.y + v1.z * p1.z + v1.w * p1.w;
            s0 = sub8sum(s0);
            s1 = sub8sum(s1);
            if (wr) {
                float* dst = (a == 0) ? g_al0 : (a == 1) ? g_ar1 : (a == 2) ? g_al2 : g_ar2;
                dst[w * HH + h0] = s0;
                dst[w * HH + h0 + 4] = s1;
            }
        }
    } else {
        int n = w - NNA;
        const float4* hp = (const float4*)(g_hB + (size_t)n * DD);
        float4 v0 = hp[lane], v1 = hp[lane + 32];
        const float4* l1 = (const float4*)(attn_l + DD);
        const float4* r0 = (const float4*)(attn_r);
#pragma unroll
        for (int a = 0; a < 2; a++) {
            const float4* P = (a == 0) ? l1 : r0;
            float4 p0 = P[lane], p1 = P[lane + 32];
            float s0 = v0.x * p0.x + v0.y * p0.y + v0.z * p0.z + v0.w * p0.w;
            float s1 = v1.x * p1.x + v1.y * p1.y + v1.z * p1.z + v1.w * p1.w;
            s0 = sub8sum(s0);
            s1 = sub8sum(s1);
            if (wr) {
                float* dst = (a == 0) ? g_al1 : g_ar0;
                dst[n * HH + h0] = s0;
                dst[n * HH + h0 + 4] = s1;
            }
        }
    }
}

// ---------------- edge pass 1: logits + segment max -------------------------
template <int REL>
__global__ void edge_attn_max(const int* __restrict__ edge) {
    int tid = blockIdx.x * blockDim.x + threadIdx.x;   // E*H threads
    if (tid >= EE * HH) return;
    int e = tid >> 3, h = tid & 7;
    int src = edge[e];
    int dst = edge[EE + e];
    const float* al = (REL == 0) ? g_al0 : (REL == 1) ? g_al1 : g_al2;
    const float* ar = (REL == 0) ? g_ar0 : (REL == 1) ? g_ar1 : g_ar2;
    float v = leaky(al[src * HH + h] + ar[dst * HH + h]);
    g_ebuf[tid] = v;
    atomicMax(&g_menc[REL][dst * HH + h], fenc(v));
}

// ---------------- edge pass 2: exp + segment sum ----------------------------
template <int REL>
__global__ void edge_exp_sum(const int* __restrict__ edge) {
    int tid = blockIdx.x * blockDim.x + threadIdx.x;
    if (tid >= EE * HH) return;
    int e = tid >> 3, h = tid & 7;
    int dst = edge[EE + e];
    float m = fdec(g_menc[REL][dst * HH + h]);
    float ex = __expf(g_ebuf[tid] - m);
    g_ebuf[tid] = ex;
    atomicAdd(&g_den[REL][dst * HH + h], ex);
}

// ---------------- edge pass 3: weighted message scatter ---------------------
template <int REL>
__global__ void edge_message(const int* __restrict__ edge) {
    int gw   = (blockIdx.x * blockDim.x + threadIdx.x) >> 5;   // one warp per edge
    int lane = threadIdx.x & 31;
    if (gw >= EE) return;
    int src = edge[gw];
    int dst = edge[EE + gw];
    const float* hsrc = (REL == 1) ? g_hB : g_hA;
    float* rel = (REL == 0) ? g_relAB : (REL == 1) ? g_relBA : g_relAA;
    const float4* hp = (const float4*)(hsrc + (size_t)src * DD);
    float4* rp = (float4*)(rel + (size_t)dst * DD);
#pragma unroll
    for (int rep = 0; rep < 2; rep++) {
        int q = lane + rep * 32;          // 64 float4 per edge row
        int h = q >> 3;
        float alpha = g_ebuf[gw * 8 + h] / g_den[REL][dst * 8 + h];
        float4 v = hp[q];
        v.x *= alpha; v.y *= alpha; v.z *= alpha; v.w *= alpha;
        atomicAdd(rp + q, v);             // sm_90+ vector float4 atomic add
    }
}

// ---------------- beta combine (relation softmax) ---------------------------
__global__ void beta_combine_A(const float* __restrict__ rl,
                               const float* __restrict__ rr,
                               float* __restrict__ out) {
    int w    = (blockIdx.x * blockDim.x + threadIdx.x) >> 5;   // warp per node
    int lane = threadIdx.x & 31;
    if (w >= NNA) return;
    const float* hp = g_hA + (size_t)w * DD;
    const float* p0 = g_relBA + (size_t)w * DD;
    const float* p1 = g_relAA + (size_t)w * DD;
    float* op = out + (size_t)w * DD;
#pragma unroll
    for (int h = 0; h < HH; h++) {
        int o = h * 32 + lane;
        float a  = hp[o];
        float e0 = p0[o];
        float e1 = p1[o];
        float wl = rl[o];
        float wr = rr[o];
        float bl = warpsum(a * wl);
        float b0 = warpsum(e0 * wr);
        float b1 = warpsum(e1 * wr);
        float b2 = warpsum(a * wr);
        float s0 = leaky(bl + b0);
        float s1 = leaky(bl + b1);
        float s2 = leaky(bl + b2);
        float mx = fmaxf(s0, fmaxf(s1, s2));
        float x0 = __expf(s0 - mx), x1 = __expf(s1 - mx), x2 = __expf(s2 - mx);
        float inv = 1.f / (x0 + x1 + x2);
        float v = (e0 * x0 + e1 * x1 + a * x2) * inv;
        op[o] = v > 0.f ? v : 0.f;
    }
}

__global__ void beta_combine_B(const float* __restrict__ rl,
                               const float* __restrict__ rr,
                               float* __restrict__ out) {
    int w    = (blockIdx.x * blockDim.x + threadIdx.x) >> 5;
    int lane = threadIdx.x & 31;
    if (w >= NNB) return;
    const float* hp = g_hB + (size_t)w * DD;
    const float* p0 = g_relAB + (size_t)w * DD;
    float* op = out + (size_t)w * DD;
#pragma unroll
    for (int h = 0; h < HH; h++) {
        int o = h * 32 + lane;
        float a  = hp[o];
        float e0 = p0[o];
        float wl = rl[o];
        float wr = rr[o];
        float bl = warpsum(a * wl);
        float b0 = warpsum(e0 * wr);
        float b1 = warpsum(a * wr);
        float s0 = leaky(bl + b0);
        float s1 = leaky(bl + b1);
        float mx = fmaxf(s0, s1);
        float x0 = __expf(s0 - mx), x1 = __expf(s1 - mx);
        float inv = 1.f / (x0 + x1);
        float v = (e0 * x0 + a * x1) * inv;
        op[o] = v > 0.f ? v : 0.f;
    }
}

// ---------------- launch -----------------------------------------------------
extern "C" void kernel_launch(void* const* d_in, const int* in_sizes, int n_in,
                              void* d_out, int out_size) {
    const float* x_A    = (const float*)d_in[0];
    const float* x_B    = (const float*)d_in[1];
    const int*   e_ab   = (const int*)d_in[2];
    const int*   e_ba   = (const int*)d_in[3];
    const int*   e_aa   = (const int*)d_in[4];
    const float* W_A    = (const float*)d_in[5];
    const float* b_A    = (const float*)d_in[6];
    const float* W_B    = (const float*)d_in[7];
    const float* b_B    = (const float*)d_in[8];
    const float* attn_l = (const float*)d_in[9];
    const float* attn_r = (const float*)d_in[10];
    const float* rel_l_A = (const float*)d_in[11];
    const float* rel_r_A = (const float*)d_in[12];
    const float* rel_l_B = (const float*)d_in[13];
    const float* rel_r_B = (const float*)d_in[14];
    float* out = (float*)d_out;

    zero_all<<<10000, 256>>>();

    dim3 gg((NNA + GBM - 1) / GBM, 256 / GBN);   // 313 x 4
    gemm_tf32<0><<<gg, 256>>>(x_A, W_A, b_A);
    gemm_tf32<1><<<gg, 256>>>(x_B, W_B, b_B);

    alphas_kernel<<<10000, 256>>>(attn_l, attn_r);   // warp per node, 80000 warps

    // relation 0: A -> B
    edge_attn_max<0><<<12500, 256>>>(e_ab);
    edge_exp_sum<0><<<12500, 256>>>(e_ab);
    edge_message<0><<<50000, 256>>>(e_ab);
    // relation 1: B -> A
    edge_attn_max<1><<<12500, 256>>>(e_ba);
    edge_exp_sum<1><<<12500, 256>>>(e_ba);
    edge_message<1><<<50000, 256>>>(e_ba);
    // relation 2: A -> A
    edge_attn_max<2><<<12500, 256>>>(e_aa);
    edge_exp_sum<2><<<12500, 256>>>(e_aa);
    edge_message<2><<<50000, 256>>>(e_aa);

    beta_combine_A<<<5000, 256>>>(rel_l_A, rel_r_A, out);
    beta_combine_B<<<5000, 256>>>(rel_l_B, rel_r_B, out + (size_t)NNA * DD);
}